// round 15
// baseline (speedup 1.0000x reference)
#include <cuda_runtime.h>
#include <cuda_fp16.h>
#include <math.h>
#include <stdint.h>

#define NUM_EMBED 8192
#define EMBED_DIM 64
#define BB 8
#define HH 64
#define WW 64
#define N_TOK   (BB*HH*WW)            /* 32768 */
#define N_ELEM  (BB*EMBED_DIM*HH*WW)  /* 2097152 */
#define HW      (HH*WW)               /* 4096 */
#define N_PART  2048

#define M_CTA   128                   /* tokens per CTA (stage 1) */
#define TN      128                   /* codes per tile */
#define N_TILES (NUM_EMBED / TN)      /* 64 */
#define NT1     256                   /* stage-1 threads (8 warps) */

// stage-1 SMEM (from 1024-aligned base):
//   A0  @ 0     : 128 rows x 128B (fp16 z, swizzled)   16384
//   B   @ 16384 : 2 bufs x [128 x 128B]                32768
//   TAB @ 49152 : 128 rows x 2 groups x 3 float2       6144
#define OFF_B    16384
#define OFF_TAB  49152
#define SMEM1_BYTES (OFF_TAB + 6144 + 1024)

#define SWZ(o) ((o) ^ (((o) >> 3) & 0x70))

// ---------------------------------------------------------------------------
// device scratch
// ---------------------------------------------------------------------------
__device__ __align__(16) __half g_e0[NUM_EMBED * EMBED_DIM];   // fp16 normalized codebook
__device__ __align__(16) float  g_enf[NUM_EMBED * EMBED_DIM];  // fp32 normalized codebook
__device__ int   g_idx[N_TOK];
__device__ int   g_flist[N_TOK];
__device__ int   g_nflag;
__device__ int   g_hist[NUM_EMBED];
__device__ float g_partial[N_PART];

// ---------------------------------------------------------------------------
// asm helpers (plain sm_80+ only)
// ---------------------------------------------------------------------------
__device__ __forceinline__ uint32_t smem_u32(const void* p) {
    uint32_t a;
    asm("{ .reg .u64 t; cvta.to.shared.u64 t, %1; cvt.u32.u64 %0, t; }" : "=r"(a) : "l"(p));
    return a;
}
#define LDSM_X4(r, addr)                                                         \
    asm volatile("ldmatrix.sync.aligned.m8n8.x4.shared.b16 {%0,%1,%2,%3}, [%4];" \
        : "=r"((r)[0]), "=r"((r)[1]), "=r"((r)[2]), "=r"((r)[3]) : "r"(addr))

#define MMA_16816(c, a, b0, b1)                                                  \
    asm volatile("mma.sync.aligned.m16n8k16.row.col.f32.f16.f16.f32 "            \
        "{%0,%1,%2,%3}, {%4,%5,%6,%7}, {%8,%9}, {%0,%1,%2,%3};"                  \
        : "+f"((c)[0]), "+f"((c)[1]), "+f"((c)[2]), "+f"((c)[3])                 \
        : "r"((a)[0]), "r"((a)[1]), "r"((a)[2]), "r"((a)[3]), "r"(b0), "r"(b1))

#define CP_ASYNC16(saddr, gptr)                                                  \
    asm volatile("cp.async.cg.shared.global [%0], [%1], 16;" :: "r"(saddr), "l"(gptr))
#define CP_COMMIT()  asm volatile("cp.async.commit_group;")
#define CP_WAIT1()   asm volatile("cp.async.wait_group 1;")
#define CP_WAIT0()   asm volatile("cp.async.wait_group 0;")

// strict (value desc, index asc) ordering
__device__ __forceinline__ bool vgt(float u, int ui, float v, int vi) {
    return (u > v) || (u == v && ui < vi);
}

// merge two sorted-3 lists (value desc, idx asc); result in a*
__device__ __forceinline__ void merge3(
    float& a0, int& x0, float& a1, int& x1, float& a2, int& x2,
    float  b0, int  y0, float  b1, int  y1, float  b2, int  y2)
{
    float o0, o1, o2; int p0, p1, p2;
    if (vgt(a0, x0, b0, y0)) {
        o0 = a0; p0 = x0;
        if (vgt(a1, x1, b0, y0)) {
            o1 = a1; p1 = x1;
            if (vgt(a2, x2, b0, y0)) { o2 = a2; p2 = x2; } else { o2 = b0; p2 = y0; }
        } else {
            o1 = b0; p1 = y0;
            if (vgt(a1, x1, b1, y1)) { o2 = a1; p2 = x1; } else { o2 = b1; p2 = y1; }
        }
    } else {
        o0 = b0; p0 = y0;
        if (vgt(b1, y1, a0, x0)) {
            o1 = b1; p1 = y1;
            if (vgt(b2, y2, a0, x0)) { o2 = b2; p2 = y2; } else { o2 = a0; p2 = x0; }
        } else {
            o1 = a0; p1 = x0;
            if (vgt(b1, y1, a1, x1)) { o2 = b1; p2 = y1; } else { o2 = a1; p2 = x1; }
        }
    }
    a0 = o0; x0 = p0; a1 = o1; x1 = p1; a2 = o2; x2 = p2;
}

// ---------------------------------------------------------------------------
// Kernel 1: zero scratch + normalize codebook -> fp16 + fp32
// ---------------------------------------------------------------------------
__global__ void vq_prep_embed(const float* __restrict__ emb) {
    int gid = blockIdx.x * 256 + threadIdx.x;
    if (threadIdx.x < 8) g_hist[blockIdx.x * 8 + threadIdx.x] = 0;
    if (gid == 0) g_nflag = 0;

    int wid  = gid >> 5;
    int lane = threadIdx.x & 31;
    if (wid >= NUM_EMBED) return;
    const float* row = emb + wid * EMBED_DIM;
    float x0 = row[lane];
    float x1 = row[lane + 32];
    float s = x0 * x0 + x1 * x1;
    #pragma unroll
    for (int o = 16; o > 0; o >>= 1) s += __shfl_xor_sync(0xFFFFFFFFu, s, o);
    float inv = 1.0f / sqrtf(s);
    #pragma unroll
    for (int h = 0; h < 2; h++) {
        int c = lane + h * 32;
        float xn = (h ? x1 : x0) * inv;
        g_e0[wid * EMBED_DIM + c]  = __float2half(xn);
        g_enf[wid * EMBED_DIM + c] = xn;
    }
}

// ---------------------------------------------------------------------------
// Kernel 2 (stage 1): 1-term fp16 GEMM + screened top-3 (value,index) lists
// + exact 3-candidate rescore certificate.
// 256 threads = 8 warps, 4(M) x 2(N). Warp tile 32 x 64. 2 CTAs/SM.
// ---------------------------------------------------------------------------
__global__ __launch_bounds__(NT1, 2)
void vq_argmax_mma(const float* __restrict__ z, float* __restrict__ idx_out_f) {
    extern __shared__ char dsm_raw[];
    const uint32_t raw   = smem_u32(dsm_raw);
    const uint32_t abase = (raw + 1023u) & ~1023u;
    char* sm = dsm_raw + (abase - raw);

    const int tid    = threadIdx.x;
    const int lane   = tid & 31;
    const int warp_m = (tid >> 5) & 3;
    const int warp_n = tid >> 7;
    const int wm0    = warp_m * 32;
    const int cn0    = warp_n * 64;
    const int grp    = lane >> 3;

    const int m0  = blockIdx.x * M_CTA;
    const int b   = m0 >> 12;
    const int hw0 = m0 & 4095;

    auto load_b = [&](int t, int p) {
        const int n0 = t * TN;
        const uint32_t sb = abase + OFF_B + p * 16384;
        #pragma unroll
        for (int q = 0; q < 4; q++) {
            int i  = tid + q * NT1;        // 0..1023
            int r  = i >> 3;
            int ch = i & 7;
            CP_ASYNC16(sb + SWZ(r * 128 + ch * 16),
                       g_e0 + (n0 + r) * EMBED_DIM + ch * 8);
        }
    };

    load_b(0, 0);
    CP_COMMIT();

    // prologue: z tile -> fp16 A0 (swizzled)
    {
        const float* zb = z + b * (EMBED_DIM * HW) + hw0;
        #pragma unroll
        for (int q = 0; q < 8; q++) {
            int i  = tid + q * NT1;        // 0..2047
            int c  = i >> 5;
            int m4 = (i & 31) << 2;
            float4 v = *(const float4*)(zb + c * HW + m4);
            float xs[4] = {v.x, v.y, v.z, v.w};
            #pragma unroll
            for (int e = 0; e < 4; e++)
                *(__half*)(sm + SWZ((m4 + e) * 128 + c * 2)) = __float2half(xs[e]);
        }
    }
    __syncthreads();

    // per-slot top-3 lists (value desc, idx asc)
    float L0v[4], L1v[4], L2v[4];
    int   L0i[4], L1i[4], L2i[4];
    #pragma unroll
    for (int s = 0; s < 4; s++) {
        L0v[s] = L1v[s] = L2v[s] = -3.0e38f;
        L0i[s] = L1i[s] = L2i[s] = 0x7FFFFFFF;
    }

    const int a_row  = wm0 + (grp & 1) * 8 + (lane & 7);
    const int b_rowL = cn0 + (grp & 1) * 8 + (lane & 7);
    const int k_off  = (grp >> 1) * 8;

    for (int t = 0; t < N_TILES; t++) {
        const int p  = t & 1;
        const int n0 = t * TN;

        if (t + 1 < N_TILES) {
            load_b(t + 1, (t + 1) & 1);
            CP_COMMIT();
            CP_WAIT1();
        } else {
            CP_WAIT0();
        }
        __syncthreads();

        float acc[2][8][4];
        #pragma unroll
        for (int i = 0; i < 2; i++)
            #pragma unroll
            for (int j = 0; j < 8; j++)
                #pragma unroll
                for (int q = 0; q < 4; q++) acc[i][j][q] = 0.0f;

        const uint32_t bbuf = abase + OFF_B + p * 16384;
        #pragma unroll
        for (int ks = 0; ks < 4; ks++) {
            const int kb = ks * 16 + k_off;
            uint32_t a0f[2][4];
            #pragma unroll
            for (int i = 0; i < 2; i++)
                LDSM_X4(a0f[i], abase + SWZ((a_row + i * 16) * 128 + kb * 2));
            #pragma unroll
            for (int j2 = 0; j2 < 4; j2++) {
                uint32_t b0r[4];
                LDSM_X4(b0r, bbuf + SWZ((b_rowL + j2 * 16) * 128 + kb * 2));
                #pragma unroll
                for (int sub = 0; sub < 2; sub++)
                    #pragma unroll
                    for (int i = 0; i < 2; i++)
                        MMA_16816(acc[i][j2 * 2 + sub], a0f[i], b0r[sub], b0r[2 + sub]);
            }
        }

        // phase 1: per-slot tile max (cheap fmax tree)
        float tm[4];
        #pragma unroll
        for (int s = 0; s < 4; s++) tm[s] = -3.0e38f;
        #pragma unroll
        for (int i = 0; i < 2; i++)
            #pragma unroll
            for (int j = 0; j < 8; j++)
                #pragma unroll
                for (int h = 0; h < 2; h++)
                    tm[i * 2 + h] = fmaxf(tm[i * 2 + h],
                                          fmaxf(acc[i][j][2 * h], acc[i][j][2 * h + 1]));

        // phase 2: insert into top-3 only if tile can contribute (tm > 3rd).
        // Scores <= 3rd-best are provably bounded by the merged global v3.
        #pragma unroll
        for (int i = 0; i < 2; i++) {
            #pragma unroll
            for (int h = 0; h < 2; h++) {
                int s = i * 2 + h;
                if (tm[s] > L2v[s]) {
                    #pragma unroll
                    for (int j = 0; j < 8; j++) {
                        int cbase = n0 + cn0 + j * 8 + (lane & 3) * 2;
                        #pragma unroll
                        for (int u = 0; u < 2; u++) {
                            float v = acc[i][j][2 * h + u];
                            if (v > L2v[s]) {
                                int idx = cbase + u;
                                if (v > L0v[s]) {
                                    L2v[s] = L1v[s]; L2i[s] = L1i[s];
                                    L1v[s] = L0v[s]; L1i[s] = L0i[s];
                                    L0v[s] = v;      L0i[s] = idx;
                                } else if (v > L1v[s]) {
                                    L2v[s] = L1v[s]; L2i[s] = L1i[s];
                                    L1v[s] = v;      L1i[s] = idx;
                                } else {
                                    L2v[s] = v;      L2i[s] = idx;
                                }
                            }
                        }
                    }
                }
            }
        }
        __syncthreads();
    }

    // quad reduce: merge sorted-3 lists across the 4 column-lanes of each token
    #pragma unroll
    for (int s = 0; s < 4; s++) {
        #pragma unroll
        for (int off = 1; off < 4; off <<= 1) {
            float b0 = __shfl_xor_sync(0xFFFFFFFFu, L0v[s], off);
            int   y0 = __shfl_xor_sync(0xFFFFFFFFu, L0i[s], off);
            float b1 = __shfl_xor_sync(0xFFFFFFFFu, L1v[s], off);
            int   y1 = __shfl_xor_sync(0xFFFFFFFFu, L1i[s], off);
            float b2 = __shfl_xor_sync(0xFFFFFFFFu, L2v[s], off);
            int   y2 = __shfl_xor_sync(0xFFFFFFFFu, L2i[s], off);
            merge3(L0v[s], L0i[s], L1v[s], L1i[s], L2v[s], L2i[s],
                   b0, y0, b1, y1, b2, y2);
        }
    }

    // table: [row][warp_n][3] float2
    float2* table = (float2*)(sm + OFF_TAB);
    if ((lane & 3) == 0) {
        #pragma unroll
        for (int s = 0; s < 4; s++) {
            int row = wm0 + (s >> 1) * 16 + (s & 1) * 8 + (lane >> 2);
            table[row * 6 + warp_n * 3 + 0] = make_float2(L0v[s], __int_as_float(L0i[s]));
            table[row * 6 + warp_n * 3 + 1] = make_float2(L1v[s], __int_as_float(L1i[s]));
            table[row * 6 + warp_n * 3 + 2] = make_float2(L2v[s], __int_as_float(L2i[s]));
        }
    }
    __syncthreads();

    if (tid < M_CTA) {
        float2 r0 = table[tid * 6 + 0];
        float2 r1 = table[tid * 6 + 1];
        float2 r2 = table[tid * 6 + 2];
        float2 q0 = table[tid * 6 + 3];
        float2 q1 = table[tid * 6 + 4];
        float2 q2 = table[tid * 6 + 5];
        float g0 = r0.x, g1 = r1.x, g2 = r2.x;
        int   i0 = __float_as_int(r0.y), i1 = __float_as_int(r1.y), i2 = __float_as_int(r2.y);
        merge3(g0, i0, g1, i1, g2, i2,
               q0.x, __float_as_int(q0.y),
               q1.x, __float_as_int(q1.y),
               q2.x, __float_as_int(q2.y));

        // exact fp32 rescore of all 3 candidates + ||z||^2
        const float* zb2 = z + b * (EMBED_DIM * HW) + hw0 + tid;
        const float4* e0 = (const float4*)(g_enf + i0 * EMBED_DIM);
        const float4* e1 = (const float4*)(g_enf + i1 * EMBED_DIM);
        const float4* e2 = (const float4*)(g_enf + i2 * EMBED_DIM);
        float d0 = 0.f, d1 = 0.f, d2 = 0.f, nn = 0.f;
        #pragma unroll
        for (int q = 0; q < 16; q++) {
            float z0 = zb2[(q * 4 + 0) * HW];
            float z1 = zb2[(q * 4 + 1) * HW];
            float z2 = zb2[(q * 4 + 2) * HW];
            float z3 = zb2[(q * 4 + 3) * HW];
            float4 v0 = e0[q], v1 = e1[q], v2 = e2[q];
            d0 += z0 * v0.x + z1 * v0.y + z2 * v0.z + z3 * v0.w;
            d1 += z0 * v1.x + z1 * v1.y + z2 * v1.z + z3 * v1.w;
            d2 += z0 * v2.x + z1 * v2.y + z2 * v2.z + z3 * v2.w;
            nn += z0 * z0 + z1 * z1 + z2 * z2 + z3 * z3;
        }
        float eps = 5.2e-4f * sqrtf(nn) + 1.0e-5f;

        // exact winner among candidates (lowest index on exact tie)
        float wv = d0; int wi = i0;
        if (d1 > wv || (d1 == wv && i1 < wi)) { wv = d1; wi = i1; }
        if (d2 > wv || (d2 == wv && i2 < wi)) { wv = d2; wi = i2; }

        int token = m0 + tid;
        g_idx[token] = wi;
        // all non-candidate codes have approx <= g2, exact <= g2 + eps
        if (wv > g2 + eps) {
            atomicAdd(&g_hist[wi], 1);
            idx_out_f[token] = (float)wi;
        } else {
            int pos = atomicAdd(&g_nflag, 1);
            g_flist[pos] = token;
        }
    }
}

// ---------------------------------------------------------------------------
// Kernel 3: exact fp32 full rescan of the (rare) uncertified tokens.
// warp per token, grid-stride. Expected count ~ tens.
// ---------------------------------------------------------------------------
__global__ __launch_bounds__(256)
void vq_fallback(const float* __restrict__ z, float* __restrict__ idx_out_f) {
    const int count = g_nflag;
    for (int i = blockIdx.x * 8 + (threadIdx.x >> 5); i < count; i += 16 * 8) {
        int lane = threadIdx.x & 31;
        int tok  = g_flist[i];
        const float* zb = z + (tok >> 12) * (EMBED_DIM * HW) + (tok & 4095);
        float zr[EMBED_DIM];
        #pragma unroll
        for (int c = 0; c < EMBED_DIM; c++) zr[c] = zb[c * HW];

        float best = -3.0e38f;
        int   bi   = 0x7FFFFFFF;
        for (int n = lane; n < NUM_EMBED; n += 32) {
            const float4* er = (const float4*)(g_enf + n * EMBED_DIM);
            float a = 0.f;
            #pragma unroll
            for (int q = 0; q < 16; q++) {
                float4 e4 = er[q];
                a += zr[q * 4 + 0] * e4.x + zr[q * 4 + 1] * e4.y
                   + zr[q * 4 + 2] * e4.z + zr[q * 4 + 3] * e4.w;
            }
            if (a > best) { best = a; bi = n; }
        }
        #pragma unroll
        for (int off = 16; off > 0; off >>= 1) {
            float ov = __shfl_xor_sync(0xFFFFFFFFu, best, off);
            int   oi = __shfl_xor_sync(0xFFFFFFFFu, bi, off);
            if (ov > best || (ov == best && oi < bi)) { best = ov; bi = oi; }
        }
        if (lane == 0) {
            g_idx[tok] = bi;
            atomicAdd(&g_hist[bi], 1);
            idx_out_f[tok] = (float)bi;
        }
    }
}

// ---------------------------------------------------------------------------
// Kernel 4: gather z_q into out, per-block loss partials
// ---------------------------------------------------------------------------
__global__ __launch_bounds__(256)
void vq_gather_loss(const float* __restrict__ z, const float* __restrict__ emb,
                    float* __restrict__ out) {
    int v = blockIdx.x * 256 + threadIdx.x;
    int e = v << 2;
    int c = (e >> 12) & 63;
    int t = ((e >> 18) << 12) | (e & 4095);

    float4 zv = *(const float4*)(z + e);
    int i0 = g_idx[t + 0];
    int i1 = g_idx[t + 1];
    int i2 = g_idx[t + 2];
    int i3 = g_idx[t + 3];
    float q0 = emb[i0 * EMBED_DIM + c];
    float q1 = emb[i1 * EMBED_DIM + c];
    float q2 = emb[i2 * EMBED_DIM + c];
    float q3 = emb[i3 * EMBED_DIM + c];
    *(float4*)(out + e) = make_float4(q0, q1, q2, q3);

    float d0 = q0 - zv.x, d1 = q1 - zv.y, d2 = q2 - zv.z, d3 = q3 - zv.w;
    float s = d0 * d0 + d1 * d1 + d2 * d2 + d3 * d3;

    #pragma unroll
    for (int o = 16; o > 0; o >>= 1) s += __shfl_xor_sync(0xFFFFFFFFu, s, o);
    __shared__ float ws[8];
    int lane = threadIdx.x & 31, wrp = threadIdx.x >> 5;
    if (lane == 0) ws[wrp] = s;
    __syncthreads();
    if (threadIdx.x == 0) {
        float acc = 0.0f;
        #pragma unroll
        for (int i = 0; i < 8; i++) acc += ws[i];
        g_partial[blockIdx.x] = acc;
    }
}

// ---------------------------------------------------------------------------
// Kernel 5: finalize loss + perplexity
// ---------------------------------------------------------------------------
__global__ __launch_bounds__(256)
void vq_finalize(float* __restrict__ out) {
    __shared__ float sh[256];
    int tid = threadIdx.x;

    float s = 0.0f;
    for (int i = tid; i < N_PART; i += 256) s += g_partial[i];
    sh[tid] = s;
    __syncthreads();
    for (int o = 128; o > 0; o >>= 1) {
        if (tid < o) sh[tid] += sh[tid + o];
        __syncthreads();
    }
    if (tid == 0) out[N_ELEM] = 1.25f * sh[0] / (float)N_ELEM;
    __syncthreads();

    float h = 0.0f;
    for (int i = tid; i < NUM_EMBED; i += 256) {
        float p = (float)g_hist[i] * (1.0f / (float)N_TOK);
        h += p * logf(p + 1e-10f);
    }
    sh[tid] = h;
    __syncthreads();
    for (int o = 128; o > 0; o >>= 1) {
        if (tid < o) sh[tid] += sh[tid + o];
        __syncthreads();
    }
    if (tid == 0) out[N_ELEM + 1] = expf(-sh[0]);
}

// ---------------------------------------------------------------------------
// Output layout (all float32): [0, N_ELEM) out | loss | perplexity | idx_map
// ---------------------------------------------------------------------------
extern "C" void kernel_launch(void* const* d_in, const int* in_sizes, int n_in,
                              void* d_out, int out_size) {
    const float* z   = (const float*)d_in[0];
    const float* emb = (const float*)d_in[1];
    float* out = (float*)d_out;

    cudaFuncSetAttribute(vq_argmax_mma, cudaFuncAttributeMaxDynamicSharedMemorySize,
                         SMEM1_BYTES);

    vq_prep_embed<<<1024, 256>>>(emb);
    vq_argmax_mma<<<N_TOK / M_CTA, NT1, SMEM1_BYTES>>>(z, out + N_ELEM + 2);
    vq_fallback<<<16, 256>>>(z, out + N_ELEM + 2);
    vq_gather_loss<<<N_PART, 256>>>(z, emb, out);
    vq_finalize<<<1, 256>>>(out);
}